// round 11
// baseline (speedup 1.0000x reference)
#include <cuda_runtime.h>
#include <cstdint>

#define BSZ    4
#define TLEN   2048
#define DMODEL 1024
#define DHEAD  64
#define NROWS  (BSZ*TLEN)

// Scratch (allocation-free rule: __device__ globals)
__device__ float g_Q[NROWS*DHEAD];
__device__ float g_K[NROWS*DHEAD];
// W fragment-pack: [sel(2)][k8g(128)][n(64)][qd(4)] -> {W[n][c], W[n][c+4]}, c=k8g*8+qd
__device__ float2 g_Wp[2*128*64*4];
// split-KV partials: [b][qt(32)][chunk(<=6)][64 rows][64 cols], plus per-row m,l
__device__ float g_part[4*32*6*64*64];
__device__ float g_pm[4*32*6*64];
__device__ float g_pl[4*32*6*64];
__device__ int   g_cnt[4*32];

// ---------------------------------------------------------------------------
// helpers
// ---------------------------------------------------------------------------
__device__ __forceinline__ unsigned f2tf(float a) {
    unsigned r;
    asm("cvt.rna.tf32.f32 %0, %1;" : "=r"(r) : "f"(a));
    return r;
}
__device__ __forceinline__ unsigned fbits(float f) { return __float_as_uint(f); }

__device__ __forceinline__ void mma_tf32(float c[4],
                                         unsigned a0, unsigned a1, unsigned a2, unsigned a3,
                                         unsigned b0, unsigned b1) {
    asm volatile(
        "mma.sync.aligned.m16n8k8.row.col.f32.tf32.tf32.f32 "
        "{%0,%1,%2,%3}, {%4,%5,%6,%7}, {%8,%9}, {%0,%1,%2,%3};"
        : "+f"(c[0]), "+f"(c[1]), "+f"(c[2]), "+f"(c[3])
        : "r"(a0), "r"(a1), "r"(a2), "r"(a3), "r"(b0), "r"(b1));
}

__device__ __forceinline__ void ldsm4(uint32_t& r0, uint32_t& r1,
                                      uint32_t& r2, uint32_t& r3, uint32_t addr) {
    asm volatile("ldmatrix.sync.aligned.m8n8.x4.shared.b16 {%0,%1,%2,%3}, [%4];"
        : "=r"(r0), "=r"(r1), "=r"(r2), "=r"(r3) : "r"(addr));
}

__device__ __forceinline__ void cp16(uint32_t dst, const void* src) {
    asm volatile("cp.async.cg.shared.global [%0], [%1], 16;" :: "r"(dst), "l"(src));
}
__device__ __forceinline__ void cpcommit() {
    asm volatile("cp.async.commit_group;");
}
template<int N> __device__ __forceinline__ void cpwait() {
    asm volatile("cp.async.wait_group %0;" :: "n"(N));
}

// ---------------------------------------------------------------------------
// Prep: pack W into tf32 fragment layout via smem staging (both GMEM sides
// coalesced). grid = 32: blockIdx -> (sel = bx>>4, kb = bx&15 : 8 k8g each).
// Also zeroes the merge counters.
// ---------------------------------------------------------------------------
__global__ __launch_bounds__(256) void prep_w(
    const float* __restrict__ Wq, const float* __restrict__ Wk)
{
    __shared__ float Ws[64][68];

    const int tid = threadIdx.x;
    const int sel = blockIdx.x >> 4;
    const int kb  = blockIdx.x & 15;
    const int c0  = kb * 64;
    const float* src = sel ? Wk : Wq;

    if (blockIdx.x == 0 && tid < BSZ * 32) g_cnt[tid] = 0;

    // load 64 rows x 64 cols, coalesced float4
    #pragma unroll
    for (int i = 0; i < 4; i++) {
        int lin = tid + 256 * i;           // 0..1023
        int r = lin >> 4, c4 = (lin & 15) * 4;
        float4 v = *(const float4*)&src[(size_t)r * DMODEL + c0 + c4];
        Ws[r][c4 + 0] = v.x; Ws[r][c4 + 1] = v.y;
        Ws[r][c4 + 2] = v.z; Ws[r][c4 + 3] = v.w;
    }
    __syncthreads();

    // write 8 k8g x 64 n x 4 qd float2, coalesced; smem reads conflict-free
    #pragma unroll
    for (int i = 0; i < 8; i++) {
        int o    = tid + 256 * i;          // 0..2047
        int k8l  = o >> 8;
        int n    = (o >> 2) & 63;
        int qd   = o & 3;
        int c    = k8l * 8 + qd;
        float w0 = Ws[n][c], w1 = Ws[n][c + 4];
        g_Wp[((size_t)(sel * 128 + kb * 8 + k8l) * 64 + n) * 4 + qd] =
            make_float2(__uint_as_float(f2tf(w0)), __uint_as_float(f2tf(w1)));
    }
}

// ---------------------------------------------------------------------------
// Fused projection (single tf32): [Q|K] = x @ [Wq|Wk]^T      (R9 version)
// BM=32, BN=128. grid = 256. 8 warps: 2 m x 4 n. occ 3.
// A-frag: 1 LDS.128 from packed smem. B-frag: 1 coalesced LDG.64 from g_Wp.
// ---------------------------------------------------------------------------
__global__ __launch_bounds__(256, 3) void proj_mma(const float* __restrict__ x)
{
    __shared__ float4 XsP[16][17];

    const int tid  = threadIdx.x;
    const int lane = tid & 31;
    const int w    = tid >> 5;
    const int gid  = lane >> 2;
    const int qd   = lane & 3;
    const int mw   = w & 1;
    const int nw   = w >> 1;
    const int row0 = blockIdx.x * 32;

    const int lr    = tid >> 3;
    const int lsg   = (tid & 7) * 4;
    const int lk8   = lsg >> 3;
    const int lhalf = (lsg >> 2) & 1;
    const int lp    = (lr & 7) + ((lr >> 4) << 3);
    const int lhi   = (lr >> 3) & 1;
    const int slotA = lhalf * 2 + lhi;

    const int sel = nw >> 1;
    const float2* wp = &g_Wp[((size_t)sel * 128 * 64 + (nw & 1) * 32 + gid) * 4 + qd];

    float acc[4][4] = {};
    float4 px = *(const float4*)&x[(size_t)(row0 + lr) * DMODEL + lsg];

    for (int kc = 0; kc < DMODEL; kc += 32) {
        const int k8g0 = kc >> 3;

        // issue all 16 B-frag LDG.64 for this chunk
        float2 bf[4][4];
        #pragma unroll
        for (int k8 = 0; k8 < 4; k8++)
            #pragma unroll
            for (int nt = 0; nt < 4; nt++)
                bf[k8][nt] = wp[((size_t)(k8g0 + k8) * 64 + nt * 8) * 4];

        __syncthreads();   // WAR: previous MMA phase done with XsP

        {
            float vx[4] = {px.x, px.y, px.z, px.w};
            #pragma unroll
            for (int j = 0; j < 4; j++)
                ((float*)&XsP[lp][lk8 * 4 + j])[slotA] =
                    __uint_as_float(f2tf(vx[j]));
        }

        int kn = (kc + 32 < DMODEL) ? kc + 32 : 0;
        px = *(const float4*)&x[(size_t)(row0 + lr) * DMODEL + kn + lsg];

        __syncthreads();   // x tile visible

        #pragma unroll
        for (int k8 = 0; k8 < 4; k8++) {
            float4 af = XsP[mw * 8 + gid][k8 * 4 + qd];      // 1 x LDS.128
            unsigned a0 = fbits(af.x), a1 = fbits(af.y);
            unsigned a2 = fbits(af.z), a3 = fbits(af.w);
            #pragma unroll
            for (int nt = 0; nt < 4; nt++)
                mma_tf32(acc[nt], a0, a1, a2, a3,
                         fbits(bf[k8][nt].x), fbits(bf[k8][nt].y));
        }
    }

    float* outp = (nw < 2) ? g_Q : g_K;
    const int r = row0 + mw * 16 + gid;
    #pragma unroll
    for (int nt = 0; nt < 4; nt++) {
        int cb = (nw & 1) * 32 + nt * 8 + 2 * qd;
        *(float2*)&outp[(size_t)r * DHEAD + cb] =
            make_float2(acc[nt][0], acc[nt][1]);
        *(float2*)&outp[(size_t)(r + 8) * DHEAD + cb] =
            make_float2(acc[nt][2], acc[nt][3]);
    }
}

// ---------------------------------------------------------------------------
// Flash attention, split-KV (chunks <= 6 tiles), LDSM fragments, in-kernel
// last-CTA merge. grid = (102, BSZ), 128 threads, 4 CTAs/SM (the ONE change
// vs the 62.1us R9 baseline). V == K (reference bug).
// ---------------------------------------------------------------------------
__global__ __launch_bounds__(128, 4) void attn_mma(float* __restrict__ out)
{
    __shared__ __align__(16) float Ks[2][64][68];
    __shared__ __align__(16) float Ps[64][68];
    __shared__ int s_last;

    const int b   = blockIdx.y;
    const int cid = blockIdx.x;

    // decode (qt, ck): nch(qt) = ceil((qt+1)/6)
    int qt = 0, ck = cid;
    for (;;) { int n = (qt + 6) / 6; if (ck < n) break; ck -= n; qt++; }
    const int ntile = qt + 1;
    const int nch   = (qt + 6) / 6;
    const int bse   = ntile / nch;
    const int ext   = ntile % nch;
    const int nkv   = bse + (ck < ext ? 1 : 0);
    const int kv0   = ck * bse + (ck < ext ? ck : ext);

    const int tid  = threadIdx.x;
    const int lane = tid & 31;
    const int w    = tid >> 5;
    const int gid  = lane >> 2;
    const int qd   = lane & 3;
    const int r0l  = w * 16 + gid;

    const int qrow0 = b * TLEN + qt * 64;
    const uint32_t ks_u32 = (uint32_t)__cvta_generic_to_shared(&Ks[0][0][0]);
    const uint32_t ps_u32 = (uint32_t)__cvta_generic_to_shared(&Ps[0][0]);

    // LDSM lane->address coords
    const int s_row  = ((lane >> 4) << 3) + (lane & 7);
    const int s_col  = ((lane >> 3) & 1) * 4;
    const int pa_row = w * 16 + ((lane >> 3) & 1) * 8 + (lane & 7);
    const int pa_col = (lane >> 4) * 4;

    auto issue_tile = [&](int buf, int ktg) {
        const float* kb = &g_K[(size_t)(b * TLEN + ktg * 64) * DHEAD];
        #pragma unroll
        for (int i = 0; i < 8; i++) {
            int lin = i * 128 + tid;
            int row = lin >> 4, sg = (lin & 15) * 4;
            cp16(ks_u32 + (uint32_t)(((buf * 64 + row) * 68 + sg) * 4),
                 kb + row * 64 + sg);
        }
        cpcommit();
    };

    issue_tile(0, kv0);
    if (nkv > 1) issue_tile(1, kv0 + 1);

    // Q fragments (held in regs whole kernel)
    unsigned aq[8][4];
    {
        const float* qp = &g_Q[(size_t)(qrow0 + r0l) * DHEAD];
        #pragma unroll
        for (int k8 = 0; k8 < 8; k8++) {
            int c = k8 * 8 + qd;
            aq[k8][0] = f2tf(qp[c]);
            aq[k8][1] = f2tf(qp[8 * DHEAD + c]);
            aq[k8][2] = f2tf(qp[c + 4]);
            aq[k8][3] = f2tf(qp[8 * DHEAD + c + 4]);
        }
    }

    if (nkv > 1) cpwait<1>(); else cpwait<0>();
    __syncthreads();

    float o[8][4] = {};
    float mr0 = -1e30f, mr1 = -1e30f, lr0 = 0.f, lr1 = 0.f;
    const float scale = 0.03125f;  // 1/sqrt(d_model=1024)

    #pragma unroll 1
    for (int kt = 0; kt < nkv; kt++) {
        const int cur = kt & 1;
        const int ktg = kv0 + kt;

        // ---- S = Q @ K^T : B-frags via ldmatrix.x4 ----
        float s[8][4] = {};
        #pragma unroll
        for (int k8 = 0; k8 < 8; k8++) {
            #pragma unroll
            for (int ntp = 0; ntp < 4; ntp++) {
                uint32_t b0, b1, b2, b3;
                uint32_t a = ks_u32 +
                    (uint32_t)(((cur * 64 + ntp * 16 + s_row) * 68 + k8 * 8 + s_col) * 4);
                ldsm4(b0, b1, b2, b3, a);
                mma_tf32(s[2*ntp],     aq[k8][0], aq[k8][1], aq[k8][2], aq[k8][3], b0, b1);
                mma_tf32(s[2*ntp + 1], aq[k8][0], aq[k8][1], aq[k8][2], aq[k8][3], b2, b3);
            }
        }
        #pragma unroll
        for (int nt = 0; nt < 8; nt++)
            #pragma unroll
            for (int j = 0; j < 4; j++)
                s[nt][j] *= scale;

        if (ktg == qt) {   // diagonal tile: causal mask
            const int ra = qt * 64 + r0l, rb = ra + 8;
            #pragma unroll
            for (int nt = 0; nt < 8; nt++) {
                int cb = ktg * 64 + nt * 8 + 2 * qd;
                if (cb     > ra) s[nt][0] = -1e30f;
                if (cb + 1 > ra) s[nt][1] = -1e30f;
                if (cb     > rb) s[nt][2] = -1e30f;
                if (cb + 1 > rb) s[nt][3] = -1e30f;
            }
        }

        // ---- warp-local softmax (rows r0l, r0l+8) ----
        float tm0 = -1e30f, tm1 = -1e30f;
        #pragma unroll
        for (int nt = 0; nt < 8; nt++) {
            tm0 = fmaxf(tm0, fmaxf(s[nt][0], s[nt][1]));
            tm1 = fmaxf(tm1, fmaxf(s[nt][2], s[nt][3]));
        }
        tm0 = fmaxf(tm0, __shfl_xor_sync(0xffffffffu, tm0, 1));
        tm0 = fmaxf(tm0, __shfl_xor_sync(0xffffffffu, tm0, 2));
        tm1 = fmaxf(tm1, __shfl_xor_sync(0xffffffffu, tm1, 1));
        tm1 = fmaxf(tm1, __shfl_xor_sync(0xffffffffu, tm1, 2));

        float mn0 = fmaxf(mr0, tm0), mn1 = fmaxf(mr1, tm1);
        float corr0 = __expf(mr0 - mn0), corr1 = __expf(mr1 - mn1);
        mr0 = mn0; mr1 = mn1;

        float ps0 = 0.f, ps1 = 0.f;
        #pragma unroll
        for (int nt = 0; nt < 8; nt++) {
            float p0 = __expf(s[nt][0] - mn0);
            float p1 = __expf(s[nt][1] - mn0);
            float p2 = __expf(s[nt][2] - mn1);
            float p3 = __expf(s[nt][3] - mn1);
            ps0 += p0 + p1;
            ps1 += p2 + p3;
            int cb = nt * 8 + 2 * qd;
            *(float2*)&Ps[r0l][cb] =
                make_float2(__uint_as_float(f2tf(p0)), __uint_as_float(f2tf(p1)));
            *(float2*)&Ps[r0l + 8][cb] =
                make_float2(__uint_as_float(f2tf(p2)), __uint_as_float(f2tf(p3)));
        }
        ps0 += __shfl_xor_sync(0xffffffffu, ps0, 1);
        ps0 += __shfl_xor_sync(0xffffffffu, ps0, 2);
        ps1 += __shfl_xor_sync(0xffffffffu, ps1, 1);
        ps1 += __shfl_xor_sync(0xffffffffu, ps1, 2);
        lr0 = lr0 * corr0 + ps0;
        lr1 = lr1 * corr1 + ps1;

        #pragma unroll
        for (int nt = 0; nt < 8; nt++) {
            o[nt][0] *= corr0; o[nt][1] *= corr0;
            o[nt][2] *= corr1; o[nt][3] *= corr1;
        }

        __syncwarp();   // Ps rows are warp-private

        // ---- O += P @ V  (V == K tile): A-frags via ldmatrix.x4 ----
        #pragma unroll
        for (int k8 = 0; k8 < 8; k8++) {
            int c = k8 * 8 + qd;
            uint32_t a0, a1, a2, a3;
            uint32_t pa = ps_u32 + (uint32_t)((pa_row * 68 + k8 * 8 + pa_col) * 4);
            ldsm4(a0, a1, a2, a3, pa);
            #pragma unroll
            for (int nt = 0; nt < 8; nt++) {
                int d = nt * 8 + gid;
                unsigned b0 = fbits(Ks[cur][c][d]);
                unsigned b1 = fbits(Ks[cur][c + 4][d]);
                mma_tf32(o[nt], a0, a1, a2, a3, b0, b1);
            }
        }

        // ---- pipeline: refill cur with tile kt+2, ensure kt+1 ready ----
        if (kt + 1 < nkv) {
            __syncthreads();
            if (kt + 2 < nkv) { issue_tile(cur, kv0 + kt + 2); cpwait<1>(); }
            else              { cpwait<0>(); }
            __syncthreads();
        }
    }

    // ---- epilogue ----
    if (nch == 1) {
        float inv0 = 1.0f / lr0, inv1 = 1.0f / lr1;
        #pragma unroll
        for (int nt = 0; nt < 8; nt++) {
            int cb = nt * 8 + 2 * qd;
            *(float2*)&out[(size_t)(qrow0 + r0l) * DHEAD + cb] =
                make_float2(o[nt][0] * inv0, o[nt][1] * inv0);
            *(float2*)&out[(size_t)(qrow0 + r0l + 8) * DHEAD + cb] =
                make_float2(o[nt][2] * inv1, o[nt][3] * inv1);
        }
        return;
    }

    // write partial (unnormalized O, m, l)
    const int pb  = (b * 32 + qt) * 6;
    const int pid = pb + ck;
    {
        float* pp = &g_part[(size_t)pid * 4096];
        #pragma unroll
        for (int nt = 0; nt < 8; nt++) {
            int cb = nt * 8 + 2 * qd;
            *(float2*)&pp[(size_t)r0l * 64 + cb]       = make_float2(o[nt][0], o[nt][1]);
            *(float2*)&pp[(size_t)(r0l + 8) * 64 + cb] = make_float2(o[nt][2], o[nt][3]);
        }
        if (qd == 0) {
            g_pm[pid * 64 + r0l]     = mr0;
            g_pm[pid * 64 + r0l + 8] = mr1;
            g_pl[pid * 64 + r0l]     = lr0;
            g_pl[pid * 64 + r0l + 8] = lr1;
        }
    }
    __threadfence();
    if (tid == 0) {
        int old = atomicAdd(&g_cnt[b * 32 + qt], 1);
        s_last = (old == nch - 1) ? 1 : 0;
    }
    __syncthreads();
    if (!s_last) return;
    __threadfence();   // acquire: other chunks' partials now visible

    // merge all nch partials (this CTA is the last one for this qt)
    float mA = -1e30f, mB = -1e30f;
    for (int i = 0; i < nch; i++) {
        mA = fmaxf(mA, g_pm[(pb + i) * 64 + r0l]);
        mB = fmaxf(mB, g_pm[(pb + i) * 64 + r0l + 8]);
    }
    float lA = 0.f, lB = 0.f;
    float accA[8][2] = {}, accB[8][2] = {};
    for (int i = 0; i < nch; i++) {
        float wA = __expf(g_pm[(pb + i) * 64 + r0l]     - mA);
        float wB = __expf(g_pm[(pb + i) * 64 + r0l + 8] - mB);
        lA += wA * g_pl[(pb + i) * 64 + r0l];
        lB += wB * g_pl[(pb + i) * 64 + r0l + 8];
        const float* qp2 = &g_part[(size_t)(pb + i) * 4096];
        #pragma unroll
        for (int nt = 0; nt < 8; nt++) {
            int cb = nt * 8 + 2 * qd;
            float2 vA = *(const float2*)&qp2[(size_t)r0l * 64 + cb];
            float2 vB = *(const float2*)&qp2[(size_t)(r0l + 8) * 64 + cb];
            accA[nt][0] += wA * vA.x; accA[nt][1] += wA * vA.y;
            accB[nt][0] += wB * vB.x; accB[nt][1] += wB * vB.y;
        }
    }
    float ivA = 1.0f / lA, ivB = 1.0f / lB;
    #pragma unroll
    for (int nt = 0; nt < 8; nt++) {
        int cb = nt * 8 + 2 * qd;
        *(float2*)&out[(size_t)(qrow0 + r0l) * DHEAD + cb] =
            make_float2(accA[nt][0] * ivA, accA[nt][1] * ivA);
        *(float2*)&out[(size_t)(qrow0 + r0l + 8) * DHEAD + cb] =
            make_float2(accB[nt][0] * ivB, accB[nt][1] * ivB);
    }
}

extern "C" void kernel_launch(void* const* d_in, const int* in_sizes, int n_in,
                              void* d_out, int out_size)
{
    const float* x  = (const float*)d_in[0];
    const float* Wq = (const float*)d_in[1];
    const float* Wk = (const float*)d_in[2];
    // d_in[3] (W_V) intentionally unused: reference computes V with W_K.
    float* out = (float*)d_out;

    prep_w  <<<32, 256>>>(Wq, Wk);
    proj_mma<<<256, 256>>>(x);
    attn_mma<<<dim3(102, BSZ), 128>>>(out);
}

// round 12
// speedup vs baseline: 1.1525x; 1.1525x over previous
#include <cuda_runtime.h>
#include <cstdint>

#define BSZ    4
#define TLEN   2048
#define DMODEL 1024
#define DHEAD  64
#define NROWS  (BSZ*TLEN)

// Scratch (allocation-free rule: __device__ globals)
__device__ float g_Q[NROWS*DHEAD];
__device__ float g_K[NROWS*DHEAD];
// W fragment-pack: [sel(2)][k8g(128)][n(64)][qd(4)] -> {W[n][c], W[n][c+4]}, c=k8g*8+qd
__device__ float2 g_Wp[2*128*64*4];
// split-KV partials: [b][qt(32)][chunk(<=6)][64 rows][64 cols], plus per-row m,l
__device__ float g_part[4*32*6*64*64];
__device__ float g_pm[4*32*6*64];
__device__ float g_pl[4*32*6*64];
__device__ int   g_cnt[4*32];

// ---------------------------------------------------------------------------
// helpers
// ---------------------------------------------------------------------------
__device__ __forceinline__ unsigned f2tf(float a) {
    unsigned r;
    asm("cvt.rna.tf32.f32 %0, %1;" : "=r"(r) : "f"(a));
    return r;
}
__device__ __forceinline__ unsigned fbits(float f) { return __float_as_uint(f); }

__device__ __forceinline__ void mma_tf32(float c[4],
                                         unsigned a0, unsigned a1, unsigned a2, unsigned a3,
                                         unsigned b0, unsigned b1) {
    asm volatile(
        "mma.sync.aligned.m16n8k8.row.col.f32.tf32.tf32.f32 "
        "{%0,%1,%2,%3}, {%4,%5,%6,%7}, {%8,%9}, {%0,%1,%2,%3};"
        : "+f"(c[0]), "+f"(c[1]), "+f"(c[2]), "+f"(c[3])
        : "r"(a0), "r"(a1), "r"(a2), "r"(a3), "r"(b0), "r"(b1));
}

__device__ __forceinline__ void ldsm4(uint32_t& r0, uint32_t& r1,
                                      uint32_t& r2, uint32_t& r3, uint32_t addr) {
    asm volatile("ldmatrix.sync.aligned.m8n8.x4.shared.b16 {%0,%1,%2,%3}, [%4];"
        : "=r"(r0), "=r"(r1), "=r"(r2), "=r"(r3) : "r"(addr));
}

__device__ __forceinline__ void cp16(uint32_t dst, const void* src) {
    asm volatile("cp.async.cg.shared.global [%0], [%1], 16;" :: "r"(dst), "l"(src));
}
__device__ __forceinline__ void cpcommit() {
    asm volatile("cp.async.commit_group;");
}
template<int N> __device__ __forceinline__ void cpwait() {
    asm volatile("cp.async.wait_group %0;" :: "n"(N));
}

// ---------------------------------------------------------------------------
// Prep: pack W into tf32 fragment layout via smem staging (both GMEM sides
// coalesced). grid = 32. Also zeroes the merge counters.
// ---------------------------------------------------------------------------
__global__ __launch_bounds__(256) void prep_w(
    const float* __restrict__ Wq, const float* __restrict__ Wk)
{
    __shared__ float Ws[64][68];

    const int tid = threadIdx.x;
    const int sel = blockIdx.x >> 4;
    const int kb  = blockIdx.x & 15;
    const int c0  = kb * 64;
    const float* src = sel ? Wk : Wq;

    if (blockIdx.x == 0 && tid < BSZ * 32) g_cnt[tid] = 0;

    #pragma unroll
    for (int i = 0; i < 4; i++) {
        int lin = tid + 256 * i;
        int r = lin >> 4, c4 = (lin & 15) * 4;
        float4 v = *(const float4*)&src[(size_t)r * DMODEL + c0 + c4];
        Ws[r][c4 + 0] = v.x; Ws[r][c4 + 1] = v.y;
        Ws[r][c4 + 2] = v.z; Ws[r][c4 + 3] = v.w;
    }
    __syncthreads();

    #pragma unroll
    for (int i = 0; i < 8; i++) {
        int o    = tid + 256 * i;
        int k8l  = o >> 8;
        int n    = (o >> 2) & 63;
        int qd   = o & 3;
        int c    = k8l * 8 + qd;
        float w0 = Ws[n][c], w1 = Ws[n][c + 4];
        g_Wp[((size_t)(sel * 128 + kb * 8 + k8l) * 64 + n) * 4 + qd] =
            make_float2(__uint_as_float(f2tf(w0)), __uint_as_float(f2tf(w1)));
    }
}

// ---------------------------------------------------------------------------
// Fused projection (single tf32): [Q|K] = x @ [Wq|Wk]^T
// BM=32, BN=128. grid = 256. 8 warps: 2 m x 4 n.
// W staged per-chunk into smem via cp.async (3-stage ring) -> B-frag = 1
// conflict-free LDS.64, W L2 traffic halved, ONE barrier per chunk.
// ---------------------------------------------------------------------------
__global__ __launch_bounds__(256, 3) void proj_mma(const float* __restrict__ x)
{
    // x tile, fragment-packed, double buffered:
    // XsP[buf][pair][k8*4+qd] = {X[r][c], X[r+8][c], X[r][c+4], X[r+8][c+4]}
    __shared__ __align__(16) float4 XsP[2][16][17];
    // W chunk ring: [buf(3)][sel(2)][k8l(4)][n(64)][qd(4)] float2 = 16KB/buf
    __shared__ __align__(16) float2 Wsm[3][2048];

    const int tid  = threadIdx.x;
    const int lane = tid & 31;
    const int w    = tid >> 5;
    const int gid  = lane >> 2;
    const int qd   = lane & 3;
    const int mw   = w & 1;
    const int nw   = w >> 1;
    const int row0 = blockIdx.x * 32;

    // x loader coords (1 float4 per chunk per thread)
    const int lr    = tid >> 3;
    const int lsg   = (tid & 7) * 4;
    const int lk8   = lsg >> 3;
    const int lhalf = (lsg >> 2) & 1;
    const int lp    = (lr & 7) + ((lr >> 4) << 3);
    const int lhi   = (lr >> 3) & 1;
    const int slotA = lhalf * 2 + lhi;

    // W copy coords: thread copies 64B of one sel-region
    const int cs    = tid >> 7;          // sel region 0/1
    const int clo   = tid & 127;         // 64B unit within 8KB region
    const uint32_t ws_u32 = (uint32_t)__cvta_generic_to_shared(&Wsm[0][0]);

    // W consumer base (float2 index within a buffer)
    const int sel   = nw >> 1;
    const int nloc0 = (nw & 1) * 32 + gid;

    // issue one 16KB W chunk (k8g0 = chunk*4) into ring buffer `buf`
    auto issue_w = [&](int buf, int chunk) {
        const float2* src = &g_Wp[((size_t)(cs * 128 + chunk * 4) * 64) * 4 + clo * 8];
        uint32_t dst = ws_u32 + (uint32_t)((buf * 2048 + cs * 1024 + clo * 8) * 8);
        #pragma unroll
        for (int j = 0; j < 4; j++)
            cp16(dst + j * 16, src + j * 2);
        cpcommit();
    };

    float acc[4][4] = {};

    // ---- prologue ----
    issue_w(0, 0);
    issue_w(1, 1);
    float4 px = *(const float4*)&x[(size_t)(row0 + lr) * DMODEL + lsg];   // x chunk 0
    {
        float vx[4] = {px.x, px.y, px.z, px.w};
        #pragma unroll
        for (int j = 0; j < 4; j++)
            ((float*)&XsP[0][lp][lk8 * 4 + j])[slotA] = __uint_as_float(f2tf(vx[j]));
    }
    px = *(const float4*)&x[(size_t)(row0 + lr) * DMODEL + 32 + lsg];     // x chunk 1
    cpwait<1>();       // W chunk 0 ready
    __syncthreads();   // XsP[0] + Wsm[0] visible

    for (int i = 0; i < 32; i++) {
        const int cur = i % 3;
        const int xb  = i & 1;

        // issue W chunk i+2 into buffer (i+2)%3 (WAR-safe: consumed in iter i-1)
        if (i + 2 < 32) issue_w((i + 2) % 3, i + 2);

        // store x chunk i+1 into XsP[xb^1]; prefetch x chunk i+2
        if (i + 1 < 32) {
            float vx[4] = {px.x, px.y, px.z, px.w};
            #pragma unroll
            for (int j = 0; j < 4; j++)
                ((float*)&XsP[xb ^ 1][lp][lk8 * 4 + j])[slotA] =
                    __uint_as_float(f2tf(vx[j]));
            int kn = (i + 2 < 32) ? (i + 2) * 32 : 0;
            px = *(const float4*)&x[(size_t)(row0 + lr) * DMODEL + kn + lsg];
        }

        // ---- MMAs for chunk i ----
        const float2* wb = &Wsm[cur][sel * 1024 + nloc0 * 4 + qd];
        #pragma unroll
        for (int k8 = 0; k8 < 4; k8++) {
            float4 af = XsP[xb][mw * 8 + gid][k8 * 4 + qd];   // 1 x LDS.128
            unsigned a0 = fbits(af.x), a1 = fbits(af.y);
            unsigned a2 = fbits(af.z), a3 = fbits(af.w);
            #pragma unroll
            for (int nt = 0; nt < 4; nt++) {
                float2 bfv = wb[(k8 * 64 + nt * 8) * 4];      // 1 x LDS.64
                mma_tf32(acc[nt], a0, a1, a2, a3, fbits(bfv.x), fbits(bfv.y));
            }
        }

        // W chunk i+1 ready; XsP[xb^1] visible
        cpwait<1>();
        __syncthreads();
    }

    float* outp = (nw < 2) ? g_Q : g_K;
    const int r = row0 + mw * 16 + gid;
    #pragma unroll
    for (int nt = 0; nt < 4; nt++) {
        int cb = (nw & 1) * 32 + nt * 8 + 2 * qd;
        *(float2*)&outp[(size_t)r * DHEAD + cb] =
            make_float2(acc[nt][0], acc[nt][1]);
        *(float2*)&outp[(size_t)(r + 8) * DHEAD + cb] =
            make_float2(acc[nt][2], acc[nt][3]);
    }
}

// ---------------------------------------------------------------------------
// Flash attention, split-KV (chunks <= 6 tiles), LDSM fragments, in-kernel
// last-CTA merge. grid = (102, BSZ), 128 threads, 3 CTAs/SM (R9 known-good).
// V == K (reference bug).
// ---------------------------------------------------------------------------
__global__ __launch_bounds__(128, 3) void attn_mma(float* __restrict__ out)
{
    __shared__ __align__(16) float Ks[2][64][68];
    __shared__ __align__(16) float Ps[64][68];
    __shared__ int s_last;

    const int b   = blockIdx.y;
    const int cid = blockIdx.x;

    // decode (qt, ck): nch(qt) = ceil((qt+1)/6)
    int qt = 0, ck = cid;
    for (;;) { int n = (qt + 6) / 6; if (ck < n) break; ck -= n; qt++; }
    const int ntile = qt + 1;
    const int nch   = (qt + 6) / 6;
    const int bse   = ntile / nch;
    const int ext   = ntile % nch;
    const int nkv   = bse + (ck < ext ? 1 : 0);
    const int kv0   = ck * bse + (ck < ext ? ck : ext);

    const int tid  = threadIdx.x;
    const int lane = tid & 31;
    const int w    = tid >> 5;
    const int gid  = lane >> 2;
    const int qd   = lane & 3;
    const int r0l  = w * 16 + gid;

    const int qrow0 = b * TLEN + qt * 64;
    const uint32_t ks_u32 = (uint32_t)__cvta_generic_to_shared(&Ks[0][0][0]);
    const uint32_t ps_u32 = (uint32_t)__cvta_generic_to_shared(&Ps[0][0]);

    const int s_row  = ((lane >> 4) << 3) + (lane & 7);
    const int s_col  = ((lane >> 3) & 1) * 4;
    const int pa_row = w * 16 + ((lane >> 3) & 1) * 8 + (lane & 7);
    const int pa_col = (lane >> 4) * 4;

    auto issue_tile = [&](int buf, int ktg) {
        const float* kb = &g_K[(size_t)(b * TLEN + ktg * 64) * DHEAD];
        #pragma unroll
        for (int i = 0; i < 8; i++) {
            int lin = i * 128 + tid;
            int row = lin >> 4, sg = (lin & 15) * 4;
            cp16(ks_u32 + (uint32_t)(((buf * 64 + row) * 68 + sg) * 4),
                 kb + row * 64 + sg);
        }
        cpcommit();
    };

    issue_tile(0, kv0);
    if (nkv > 1) issue_tile(1, kv0 + 1);

    unsigned aq[8][4];
    {
        const float* qp = &g_Q[(size_t)(qrow0 + r0l) * DHEAD];
        #pragma unroll
        for (int k8 = 0; k8 < 8; k8++) {
            int c = k8 * 8 + qd;
            aq[k8][0] = f2tf(qp[c]);
            aq[k8][1] = f2tf(qp[8 * DHEAD + c]);
            aq[k8][2] = f2tf(qp[c + 4]);
            aq[k8][3] = f2tf(qp[8 * DHEAD + c + 4]);
        }
    }

    if (nkv > 1) cpwait<1>(); else cpwait<0>();
    __syncthreads();

    float o[8][4] = {};
    float mr0 = -1e30f, mr1 = -1e30f, lr0 = 0.f, lr1 = 0.f;
    const float scale = 0.03125f;  // 1/sqrt(d_model=1024)

    #pragma unroll 1
    for (int kt = 0; kt < nkv; kt++) {
        const int cur = kt & 1;
        const int ktg = kv0 + kt;

        float s[8][4] = {};
        #pragma unroll
        for (int k8 = 0; k8 < 8; k8++) {
            #pragma unroll
            for (int ntp = 0; ntp < 4; ntp++) {
                uint32_t b0, b1, b2, b3;
                uint32_t a = ks_u32 +
                    (uint32_t)(((cur * 64 + ntp * 16 + s_row) * 68 + k8 * 8 + s_col) * 4);
                ldsm4(b0, b1, b2, b3, a);
                mma_tf32(s[2*ntp],     aq[k8][0], aq[k8][1], aq[k8][2], aq[k8][3], b0, b1);
                mma_tf32(s[2*ntp + 1], aq[k8][0], aq[k8][1], aq[k8][2], aq[k8][3], b2, b3);
            }
        }
        #pragma unroll
        for (int nt = 0; nt < 8; nt++)
            #pragma unroll
            for (int j = 0; j < 4; j++)
                s[nt][j] *= scale;

        if (ktg == qt) {
            const int ra = qt * 64 + r0l, rb = ra + 8;
            #pragma unroll
            for (int nt = 0; nt < 8; nt++) {
                int cb = ktg * 64 + nt * 8 + 2 * qd;
                if (cb     > ra) s[nt][0] = -1e30f;
                if (cb + 1 > ra) s[nt][1] = -1e30f;
                if (cb     > rb) s[nt][2] = -1e30f;
                if (cb + 1 > rb) s[nt][3] = -1e30f;
            }
        }

        float tm0 = -1e30f, tm1 = -1e30f;
        #pragma unroll
        for (int nt = 0; nt < 8; nt++) {
            tm0 = fmaxf(tm0, fmaxf(s[nt][0], s[nt][1]));
            tm1 = fmaxf(tm1, fmaxf(s[nt][2], s[nt][3]));
        }
        tm0 = fmaxf(tm0, __shfl_xor_sync(0xffffffffu, tm0, 1));
        tm0 = fmaxf(tm0, __shfl_xor_sync(0xffffffffu, tm0, 2));
        tm1 = fmaxf(tm1, __shfl_xor_sync(0xffffffffu, tm1, 1));
        tm1 = fmaxf(tm1, __shfl_xor_sync(0xffffffffu, tm1, 2));

        float mn0 = fmaxf(mr0, tm0), mn1 = fmaxf(mr1, tm1);
        float corr0 = __expf(mr0 - mn0), corr1 = __expf(mr1 - mn1);
        mr0 = mn0; mr1 = mn1;

        float ps0 = 0.f, ps1 = 0.f;
        #pragma unroll
        for (int nt = 0; nt < 8; nt++) {
            float p0 = __expf(s[nt][0] - mn0);
            float p1 = __expf(s[nt][1] - mn0);
            float p2 = __expf(s[nt][2] - mn1);
            float p3 = __expf(s[nt][3] - mn1);
            ps0 += p0 + p1;
            ps1 += p2 + p3;
            int cb = nt * 8 + 2 * qd;
            *(float2*)&Ps[r0l][cb] =
                make_float2(__uint_as_float(f2tf(p0)), __uint_as_float(f2tf(p1)));
            *(float2*)&Ps[r0l + 8][cb] =
                make_float2(__uint_as_float(f2tf(p2)), __uint_as_float(f2tf(p3)));
        }
        ps0 += __shfl_xor_sync(0xffffffffu, ps0, 1);
        ps0 += __shfl_xor_sync(0xffffffffu, ps0, 2);
        ps1 += __shfl_xor_sync(0xffffffffu, ps1, 1);
        ps1 += __shfl_xor_sync(0xffffffffu, ps1, 2);
        lr0 = lr0 * corr0 + ps0;
        lr1 = lr1 * corr1 + ps1;

        #pragma unroll
        for (int nt = 0; nt < 8; nt++) {
            o[nt][0] *= corr0; o[nt][1] *= corr0;
            o[nt][2] *= corr1; o[nt][3] *= corr1;
        }

        __syncwarp();

        #pragma unroll
        for (int k8 = 0; k8 < 8; k8++) {
            int c = k8 * 8 + qd;
            uint32_t a0, a1, a2, a3;
            uint32_t pa = ps_u32 + (uint32_t)((pa_row * 68 + k8 * 8 + pa_col) * 4);
            ldsm4(a0, a1, a2, a3, pa);
            #pragma unroll
            for (int nt = 0; nt < 8; nt++) {
                int d = nt * 8 + gid;
                unsigned b0 = fbits(Ks[cur][c][d]);
                unsigned b1 = fbits(Ks[cur][c + 4][d]);
                mma_tf32(o[nt], a0, a1, a2, a3, b0, b1);
            }
        }

        if (kt + 1 < nkv) {
            __syncthreads();
            if (kt + 2 < nkv) { issue_tile(cur, kv0 + kt + 2); cpwait<1>(); }
            else              { cpwait<0>(); }
            __syncthreads();
        }
    }

    if (nch == 1) {
        float inv0 = 1.0f / lr0, inv1 = 1.0f / lr1;
        #pragma unroll
        for (int nt = 0; nt < 8; nt++) {
            int cb = nt * 8 + 2 * qd;
            *(float2*)&out[(size_t)(qrow0 + r0l) * DHEAD + cb] =
                make_float2(o[nt][0] * inv0, o[nt][1] * inv0);
            *(float2*)&out[(size_t)(qrow0 + r0l + 8) * DHEAD + cb] =
                make_float2(o[nt][2] * inv1, o[nt][3] * inv1);
        }
        return;
    }

    const int pb  = (b * 32 + qt) * 6;
    const int pid = pb + ck;
    {
        float* pp = &g_part[(size_t)pid * 4096];
        #pragma unroll
        for (int nt = 0; nt < 8; nt++) {
            int cb = nt * 8 + 2 * qd;
            *(float2*)&pp[(size_t)r0l * 64 + cb]       = make_float2(o[nt][0], o[nt][1]);
            *(float2*)&pp[(size_t)(r0l + 8) * 64 + cb] = make_float2(o[nt][2], o[nt][3]);
        }
        if (qd == 0) {
            g_pm[pid * 64 + r0l]     = mr0;
            g_pm[pid * 64 + r0l + 8] = mr1;
            g_pl[pid * 64 + r0l]     = lr0;
            g_pl[pid * 64 + r0l + 8] = lr1;
        }
    }
    __threadfence();
    if (tid == 0) {
        int old = atomicAdd(&g_cnt[b * 32 + qt], 1);
        s_last = (old == nch - 1) ? 1 : 0;
    }
    __syncthreads();
    if (!s_last) return;
    __threadfence();

    float mA = -1e30f, mB = -1e30f;
    for (int i = 0; i < nch; i++) {
        mA = fmaxf(mA, g_pm[(pb + i) * 64 + r0l]);
        mB = fmaxf(mB, g_pm[(pb + i) * 64 + r0l + 8]);
    }
    float lA = 0.f, lB = 0.f;
    float accA[8][2] = {}, accB[8][2] = {};
    for (int i = 0; i < nch; i++) {
        float wA = __expf(g_pm[(pb + i) * 64 + r0l]     - mA);
        float wB = __expf(g_pm[(pb + i) * 64 + r0l + 8] - mB);
        lA += wA * g_pl[(pb + i) * 64 + r0l];
        lB += wB * g_pl[(pb + i) * 64 + r0l + 8];
        const float* qp2 = &g_part[(size_t)(pb + i) * 4096];
        #pragma unroll
        for (int nt = 0; nt < 8; nt++) {
            int cb = nt * 8 + 2 * qd;
            float2 vA = *(const float2*)&qp2[(size_t)r0l * 64 + cb];
            float2 vB = *(const float2*)&qp2[(size_t)(r0l + 8) * 64 + cb];
            accA[nt][0] += wA * vA.x; accA[nt][1] += wA * vA.y;
            accB[nt][0] += wB * vB.x; accB[nt][1] += wB * vB.y;
        }
    }
    float ivA = 1.0f / lA, ivB = 1.0f / lB;
    #pragma unroll
    for (int nt = 0; nt < 8; nt++) {
        int cb = nt * 8 + 2 * qd;
        *(float2*)&out[(size_t)(qrow0 + r0l) * DHEAD + cb] =
            make_float2(accA[nt][0] * ivA, accA[nt][1] * ivA);
        *(float2*)&out[(size_t)(qrow0 + r0l + 8) * DHEAD + cb] =
            make_float2(accB[nt][0] * ivB, accB[nt][1] * ivB);
    }
}

extern "C" void kernel_launch(void* const* d_in, const int* in_sizes, int n_in,
                              void* d_out, int out_size)
{
    const float* x  = (const float*)d_in[0];
    const float* Wq = (const float*)d_in[1];
    const float* Wk = (const float*)d_in[2];
    // d_in[3] (W_V) intentionally unused: reference computes V with W_K.
    float* out = (float*)d_out;

    prep_w  <<<32, 256>>>(Wq, Wk);
    proj_mma<<<256, 256>>>(x);
    attn_mma<<<dim3(102, BSZ), 128>>>(out);
}

// round 13
// speedup vs baseline: 1.4475x; 1.2560x over previous
#include <cuda_runtime.h>
#include <cstdint>

#define BSZ    4
#define TLEN   2048
#define DMODEL 1024
#define DHEAD  64
#define NROWS  (BSZ*TLEN)

// Scratch (allocation-free rule: __device__ globals)
__device__ float g_Q[NROWS*DHEAD];
__device__ float g_K[NROWS*DHEAD];
// W fragment-pack: [sel(2)][k8g(128)][n(64)][qd(4)] -> {W[n][c], W[n][c+4]}, c=k8g*8+qd
__device__ float2 g_Wp[2*128*64*4];
// split-KV partials: [b][qt(16)][chunk(<=8)][128 rows][64 cols], plus per-row m,l
__device__ float g_part[4*16*8*128*64];
__device__ float g_pm[4*16*8*128];
__device__ float g_pl[4*16*8*128];
__device__ int   g_cnt[4*16];

// ---------------------------------------------------------------------------
// helpers
// ---------------------------------------------------------------------------
__device__ __forceinline__ unsigned f2tf(float a) {
    unsigned r;
    asm("cvt.rna.tf32.f32 %0, %1;" : "=r"(r) : "f"(a));
    return r;
}
__device__ __forceinline__ unsigned fbits(float f) { return __float_as_uint(f); }

__device__ __forceinline__ void mma_tf32(float c[4],
                                         unsigned a0, unsigned a1, unsigned a2, unsigned a3,
                                         unsigned b0, unsigned b1) {
    asm volatile(
        "mma.sync.aligned.m16n8k8.row.col.f32.tf32.tf32.f32 "
        "{%0,%1,%2,%3}, {%4,%5,%6,%7}, {%8,%9}, {%0,%1,%2,%3};"
        : "+f"(c[0]), "+f"(c[1]), "+f"(c[2]), "+f"(c[3])
        : "r"(a0), "r"(a1), "r"(a2), "r"(a3), "r"(b0), "r"(b1));
}

__device__ __forceinline__ void ldsm4(uint32_t& r0, uint32_t& r1,
                                      uint32_t& r2, uint32_t& r3, uint32_t addr) {
    asm volatile("ldmatrix.sync.aligned.m8n8.x4.shared.b16 {%0,%1,%2,%3}, [%4];"
        : "=r"(r0), "=r"(r1), "=r"(r2), "=r"(r3) : "r"(addr));
}

__device__ __forceinline__ void cp16(uint32_t dst, const void* src) {
    asm volatile("cp.async.cg.shared.global [%0], [%1], 16;" :: "r"(dst), "l"(src));
}
__device__ __forceinline__ void cpcommit() {
    asm volatile("cp.async.commit_group;");
}
template<int N> __device__ __forceinline__ void cpwait() {
    asm volatile("cp.async.wait_group %0;" :: "n"(N));
}

// ---------------------------------------------------------------------------
// Prep: pack W into tf32 fragment layout via smem staging (both GMEM sides
// coalesced). grid = 32. Also zeroes the merge counters.  (R9 version)
// ---------------------------------------------------------------------------
__global__ __launch_bounds__(256) void prep_w(
    const float* __restrict__ Wq, const float* __restrict__ Wk)
{
    __shared__ float Ws[64][68];

    const int tid = threadIdx.x;
    const int sel = blockIdx.x >> 4;
    const int kb  = blockIdx.x & 15;
    const int c0  = kb * 64;
    const float* src = sel ? Wk : Wq;

    if (blockIdx.x == 0 && tid < BSZ * 16) g_cnt[tid] = 0;

    #pragma unroll
    for (int i = 0; i < 4; i++) {
        int lin = tid + 256 * i;
        int r = lin >> 4, c4 = (lin & 15) * 4;
        float4 v = *(const float4*)&src[(size_t)r * DMODEL + c0 + c4];
        Ws[r][c4 + 0] = v.x; Ws[r][c4 + 1] = v.y;
        Ws[r][c4 + 2] = v.z; Ws[r][c4 + 3] = v.w;
    }
    __syncthreads();

    #pragma unroll
    for (int i = 0; i < 8; i++) {
        int o    = tid + 256 * i;
        int k8l  = o >> 8;
        int n    = (o >> 2) & 63;
        int qd   = o & 3;
        int c    = k8l * 8 + qd;
        float w0 = Ws[n][c], w1 = Ws[n][c + 4];
        g_Wp[((size_t)(sel * 128 + kb * 8 + k8l) * 64 + n) * 4 + qd] =
            make_float2(__uint_as_float(f2tf(w0)), __uint_as_float(f2tf(w1)));
    }
}

// ---------------------------------------------------------------------------
// Fused projection (single tf32): [Q|K] = x @ [Wq|Wk]^T      (R9 version)
// BM=32, BN=128. grid = 256. 8 warps: 2 m x 4 n. occ 3.
// A-frag: 1 LDS.128 from packed smem. B-frag: 1 coalesced LDG.64 from g_Wp.
// ---------------------------------------------------------------------------
__global__ __launch_bounds__(256, 3) void proj_mma(const float* __restrict__ x)
{
    __shared__ float4 XsP[16][17];

    const int tid  = threadIdx.x;
    const int lane = tid & 31;
    const int w    = tid >> 5;
    const int gid  = lane >> 2;
    const int qd   = lane & 3;
    const int mw   = w & 1;
    const int nw   = w >> 1;
    const int row0 = blockIdx.x * 32;

    const int lr    = tid >> 3;
    const int lsg   = (tid & 7) * 4;
    const int lk8   = lsg >> 3;
    const int lhalf = (lsg >> 2) & 1;
    const int lp    = (lr & 7) + ((lr >> 4) << 3);
    const int lhi   = (lr >> 3) & 1;
    const int slotA = lhalf * 2 + lhi;

    const int sel = nw >> 1;
    const float2* wp = &g_Wp[((size_t)sel * 128 * 64 + (nw & 1) * 32 + gid) * 4 + qd];

    float acc[4][4] = {};
    float4 px = *(const float4*)&x[(size_t)(row0 + lr) * DMODEL + lsg];

    for (int kc = 0; kc < DMODEL; kc += 32) {
        const int k8g0 = kc >> 3;

        float2 bf[4][4];
        #pragma unroll
        for (int k8 = 0; k8 < 4; k8++)
            #pragma unroll
            for (int nt = 0; nt < 4; nt++)
                bf[k8][nt] = wp[((size_t)(k8g0 + k8) * 64 + nt * 8) * 4];

        __syncthreads();   // WAR: previous MMA phase done with XsP

        {
            float vx[4] = {px.x, px.y, px.z, px.w};
            #pragma unroll
            for (int j = 0; j < 4; j++)
                ((float*)&XsP[lp][lk8 * 4 + j])[slotA] =
                    __uint_as_float(f2tf(vx[j]));
        }

        int kn = (kc + 32 < DMODEL) ? kc + 32 : 0;
        px = *(const float4*)&x[(size_t)(row0 + lr) * DMODEL + kn + lsg];

        __syncthreads();   // x tile visible

        #pragma unroll
        for (int k8 = 0; k8 < 4; k8++) {
            float4 af = XsP[mw * 8 + gid][k8 * 4 + qd];      // 1 x LDS.128
            unsigned a0 = fbits(af.x), a1 = fbits(af.y);
            unsigned a2 = fbits(af.z), a3 = fbits(af.w);
            #pragma unroll
            for (int nt = 0; nt < 4; nt++)
                mma_tf32(acc[nt], a0, a1, a2, a3,
                         fbits(bf[k8][nt].x), fbits(bf[k8][nt].y));
        }
    }

    float* outp = (nw < 2) ? g_Q : g_K;
    const int r = row0 + mw * 16 + gid;
    #pragma unroll
    for (int nt = 0; nt < 4; nt++) {
        int cb = (nw & 1) * 32 + nt * 8 + 2 * qd;
        *(float2*)&outp[(size_t)r * DHEAD + cb] =
            make_float2(acc[nt][0], acc[nt][1]);
        *(float2*)&outp[(size_t)(r + 8) * DHEAD + cb] =
            make_float2(acc[nt][2], acc[nt][3]);
    }
}

// ---------------------------------------------------------------------------
// Flash attention, BM=128 / 8 warps (each warp owns 16 full rows ->
// warp-local softmax). Split-KV in SUPER-tiles (128 cols = 2 kv-tiles),
// <=2 super-tiles per chunk so the diagonal pair stays together.
// grid = (72, BSZ), 256 threads, 2 CTAs/SM (dynamic smem 68KB).
// LDSM fragments, in-kernel last-CTA merge. V == K (reference bug).
// ---------------------------------------------------------------------------
__global__ __launch_bounds__(256, 2) void attn_mma(float* __restrict__ out)
{
    extern __shared__ __align__(16) char dsm[];
    float (*Ks)[64][68] = (float (*)[64][68])dsm;              // Ks[2][64][68]
    float (*Ps)[68]     = (float (*)[68])(dsm + 34816);        // Ps[128][68]
    __shared__ int s_last;

    const int b   = blockIdx.y;
    const int cid = blockIdx.x;

    // decode (qt, ck): qt = 128-row q-tile (0..15), nch(qt) = ceil((qt+1)/2)
    int qt = 0, ck = cid;
    for (;;) { int n = (qt + 2) >> 1; if (ck < n) break; ck -= n; qt++; }
    const int nsup = qt + 1;            // super-tiles (128 cols each)
    const int nch  = (qt + 2) >> 1;
    const int bs   = nsup / nch;
    const int ex   = nsup % nch;
    const int nsupc = bs + (ck < ex ? 1 : 0);
    const int sup0  = ck * bs + (ck < ex ? ck : ex);
    const int kv0   = sup0 * 2;         // in 64-col kv tiles
    const int nkv   = nsupc * 2;        // 2 or 4

    const int tid  = threadIdx.x;
    const int lane = tid & 31;
    const int w    = tid >> 5;          // 0..7
    const int gid  = lane >> 2;
    const int qd   = lane & 3;
    const int r0l  = w * 16 + gid;      // 0..127

    const int qrow0 = b * TLEN + qt * 128;
    const uint32_t ks_u32 = (uint32_t)__cvta_generic_to_shared(dsm);
    const uint32_t ps_u32 = (uint32_t)__cvta_generic_to_shared(dsm + 34816);

    // LDSM lane->address coords
    const int s_row  = ((lane >> 4) << 3) + (lane & 7);
    const int s_col  = ((lane >> 3) & 1) * 4;
    const int pa_row = w * 16 + ((lane >> 3) & 1) * 8 + (lane & 7);
    const int pa_col = (lane >> 4) * 4;

    // cp.async K-tile issue: 64x64 f32 tile = 1024 float4, 4 per thread
    auto issue_tile = [&](int buf, int ktg) {
        const float* kb = &g_K[(size_t)(b * TLEN + ktg * 64) * DHEAD];
        #pragma unroll
        for (int i = 0; i < 4; i++) {
            int lin = i * 256 + tid;
            int row = lin >> 4, sg = (lin & 15) * 4;
            cp16(ks_u32 + (uint32_t)(((buf * 64 + row) * 68 + sg) * 4),
                 kb + row * 64 + sg);
        }
        cpcommit();
    };

    issue_tile(0, kv0);
    issue_tile(1, kv0 + 1);   // nkv >= 2 always

    // Q fragments (held in regs whole kernel)
    unsigned aq[8][4];
    {
        const float* qp = &g_Q[(size_t)(qrow0 + r0l) * DHEAD];
        #pragma unroll
        for (int k8 = 0; k8 < 8; k8++) {
            int c = k8 * 8 + qd;
            aq[k8][0] = f2tf(qp[c]);
            aq[k8][1] = f2tf(qp[8 * DHEAD + c]);
            aq[k8][2] = f2tf(qp[c + 4]);
            aq[k8][3] = f2tf(qp[8 * DHEAD + c + 4]);
        }
    }

    cpwait<1>();
    __syncthreads();

    float o[8][4] = {};
    // m init: -3e29 sentinel so a fully-masked tile (-1e30) never becomes the
    // running max with exp(s - m) = exp(0); exp(-1e30 + 3e29) underflows to 0.
    float mr0 = -3e29f, mr1 = -3e29f, lr0 = 0.f, lr1 = 0.f;
    const float scale = 0.03125f;  // 1/sqrt(d_model=1024)

    #pragma unroll 1
    for (int kt = 0; kt < nkv; kt++) {
        const int cur = kt & 1;
        const int ktg = kv0 + kt;

        // ---- S = Q @ K^T : B-frags via ldmatrix.x4 ----
        float s[8][4] = {};
        #pragma unroll
        for (int k8 = 0; k8 < 8; k8++) {
            #pragma unroll
            for (int ntp = 0; ntp < 4; ntp++) {
                uint32_t b0, b1, b2, b3;
                uint32_t a = ks_u32 +
                    (uint32_t)(((cur * 64 + ntp * 16 + s_row) * 68 + k8 * 8 + s_col) * 4);
                ldsm4(b0, b1, b2, b3, a);
                mma_tf32(s[2*ntp],     aq[k8][0], aq[k8][1], aq[k8][2], aq[k8][3], b0, b1);
                mma_tf32(s[2*ntp + 1], aq[k8][0], aq[k8][1], aq[k8][2], aq[k8][3], b2, b3);
            }
        }
        #pragma unroll
        for (int nt = 0; nt < 8; nt++)
            #pragma unroll
            for (int j = 0; j < 4; j++)
                s[nt][j] *= scale;

        if (ktg >= 2 * qt) {   // diagonal super-tile: causal mask
            const int ra = qt * 128 + r0l, rb = ra + 8;
            #pragma unroll
            for (int nt = 0; nt < 8; nt++) {
                int cb = ktg * 64 + nt * 8 + 2 * qd;
                if (cb     > ra) s[nt][0] = -1e30f;
                if (cb + 1 > ra) s[nt][1] = -1e30f;
                if (cb     > rb) s[nt][2] = -1e30f;
                if (cb + 1 > rb) s[nt][3] = -1e30f;
            }
        }

        // ---- warp-local softmax (rows r0l, r0l+8) ----
        float tm0 = -1e30f, tm1 = -1e30f;
        #pragma unroll
        for (int nt = 0; nt < 8; nt++) {
            tm0 = fmaxf(tm0, fmaxf(s[nt][0], s[nt][1]));
            tm1 = fmaxf(tm1, fmaxf(s[nt][2], s[nt][3]));
        }
        tm0 = fmaxf(tm0, __shfl_xor_sync(0xffffffffu, tm0, 1));
        tm0 = fmaxf(tm0, __shfl_xor_sync(0xffffffffu, tm0, 2));
        tm1 = fmaxf(tm1, __shfl_xor_sync(0xffffffffu, tm1, 1));
        tm1 = fmaxf(tm1, __shfl_xor_sync(0xffffffffu, tm1, 2));

        float mn0 = fmaxf(mr0, tm0), mn1 = fmaxf(mr1, tm1);
        float corr0 = __expf(mr0 - mn0), corr1 = __expf(mr1 - mn1);
        mr0 = mn0; mr1 = mn1;

        float ps0 = 0.f, ps1 = 0.f;
        #pragma unroll
        for (int nt = 0; nt < 8; nt++) {
            float p0 = __expf(s[nt][0] - mn0);
            float p1 = __expf(s[nt][1] - mn0);
            float p2 = __expf(s[nt][2] - mn1);
            float p3 = __expf(s[nt][3] - mn1);
            ps0 += p0 + p1;
            ps1 += p2 + p3;
            int cb = nt * 8 + 2 * qd;
            *(float2*)&Ps[r0l][cb] =
                make_float2(__uint_as_float(f2tf(p0)), __uint_as_float(f2tf(p1)));
            *(float2*)&Ps[r0l + 8][cb] =
                make_float2(__uint_as_float(f2tf(p2)), __uint_as_float(f2tf(p3)));
        }
        ps0 += __shfl_xor_sync(0xffffffffu, ps0, 1);
        ps0 += __shfl_xor_sync(0xffffffffu, ps0, 2);
        ps1 += __shfl_xor_sync(0xffffffffu, ps1, 1);
        ps1 += __shfl_xor_sync(0xffffffffu, ps1, 2);
        lr0 = lr0 * corr0 + ps0;
        lr1 = lr1 * corr1 + ps1;

        #pragma unroll
        for (int nt = 0; nt < 8; nt++) {
            o[nt][0] *= corr0; o[nt][1] *= corr0;
            o[nt][2] *= corr1; o[nt][3] *= corr1;
        }

        __syncwarp();   // Ps rows are warp-private

        // ---- O += P @ V  (V == K tile): A-frags via ldmatrix.x4 ----
        #pragma unroll
        for (int k8 = 0; k8 < 8; k8++) {
            int c = k8 * 8 + qd;
            uint32_t a0, a1, a2, a3;
            uint32_t pa = ps_u32 + (uint32_t)((pa_row * 68 + k8 * 8 + pa_col) * 4);
            ldsm4(a0, a1, a2, a3, pa);
            #pragma unroll
            for (int nt = 0; nt < 8; nt++) {
                int d = nt * 8 + gid;
                unsigned b0 = fbits(Ks[cur][c][d]);
                unsigned b1 = fbits(Ks[cur][c + 4][d]);
                mma_tf32(o[nt], a0, a1, a2, a3, b0, b1);
            }
        }

        // ---- pipeline: refill cur with tile kt+2, ensure kt+1 ready ----
        if (kt + 1 < nkv) {
            __syncthreads();
            if (kt + 2 < nkv) { issue_tile(cur, kv0 + kt + 2); cpwait<1>(); }
            else              { cpwait<0>(); }
            __syncthreads();
        }
    }

    // ---- epilogue ----
    if (nch == 1) {
        float inv0 = 1.0f / lr0, inv1 = 1.0f / lr1;
        #pragma unroll
        for (int nt = 0; nt < 8; nt++) {
            int cb = nt * 8 + 2 * qd;
            *(float2*)&out[(size_t)(qrow0 + r0l) * DHEAD + cb] =
                make_float2(o[nt][0] * inv0, o[nt][1] * inv0);
            *(float2*)&out[(size_t)(qrow0 + r0l + 8) * DHEAD + cb] =
                make_float2(o[nt][2] * inv1, o[nt][3] * inv1);
        }
        return;
    }

    // write partial (unnormalized O, m, l)
    const int pb  = (b * 16 + qt) * 8;
    const int pid = pb + ck;
    {
        float* pp = &g_part[(size_t)pid * 8192];
        #pragma unroll
        for (int nt = 0; nt < 8; nt++) {
            int cb = nt * 8 + 2 * qd;
            *(float2*)&pp[(size_t)r0l * 64 + cb]       = make_float2(o[nt][0], o[nt][1]);
            *(float2*)&pp[(size_t)(r0l + 8) * 64 + cb] = make_float2(o[nt][2], o[nt][3]);
        }
        if (qd == 0) {
            g_pm[pid * 128 + r0l]     = mr0;
            g_pm[pid * 128 + r0l + 8] = mr1;
            g_pl[pid * 128 + r0l]     = lr0;
            g_pl[pid * 128 + r0l + 8] = lr1;
        }
    }
    __threadfence();
    if (tid == 0) {
        int old = atomicAdd(&g_cnt[b * 16 + qt], 1);
        s_last = (old == nch - 1) ? 1 : 0;
    }
    __syncthreads();
    if (!s_last) return;
    __threadfence();   // acquire: other chunks' partials now visible

    // merge all nch partials (this CTA is the last one for this qt)
    float mA = -1e30f, mB = -1e30f;
    for (int i = 0; i < nch; i++) {
        mA = fmaxf(mA, g_pm[(pb + i) * 128 + r0l]);
        mB = fmaxf(mB, g_pm[(pb + i) * 128 + r0l + 8]);
    }
    float lA = 0.f, lB = 0.f;
    float accA[8][2] = {}, accB[8][2] = {};
    for (int i = 0; i < nch; i++) {
        float wA = __expf(g_pm[(pb + i) * 128 + r0l]     - mA);
        float wB = __expf(g_pm[(pb + i) * 128 + r0l + 8] - mB);
        lA += wA * g_pl[(pb + i) * 128 + r0l];
        lB += wB * g_pl[(pb + i) * 128 + r0l + 8];
        const float* qp2 = &g_part[(size_t)(pb + i) * 8192];
        #pragma unroll
        for (int nt = 0; nt < 8; nt++) {
            int cb = nt * 8 + 2 * qd;
            float2 vA = *(const float2*)&qp2[(size_t)r0l * 64 + cb];
            float2 vB = *(const float2*)&qp2[(size_t)(r0l + 8) * 64 + cb];
            accA[nt][0] += wA * vA.x; accA[nt][1] += wA * vA.y;
            accB[nt][0] += wB * vB.x; accB[nt][1] += wB * vB.y;
        }
    }
    float ivA = 1.0f / lA, ivB = 1.0f / lB;
    #pragma unroll
    for (int nt = 0; nt < 8; nt++) {
        int cb = nt * 8 + 2 * qd;
        *(float2*)&out[(size_t)(qrow0 + r0l) * DHEAD + cb] =
            make_float2(accA[nt][0] * ivA, accA[nt][1] * ivA);
        *(float2*)&out[(size_t)(qrow0 + r0l + 8) * DHEAD + cb] =
            make_float2(accB[nt][0] * ivB, accB[nt][1] * ivB);
    }
}

extern "C" void kernel_launch(void* const* d_in, const int* in_sizes, int n_in,
                              void* d_out, int out_size)
{
    const float* x  = (const float*)d_in[0];
    const float* Wq = (const float*)d_in[1];
    const float* Wk = (const float*)d_in[2];
    // d_in[3] (W_V) intentionally unused: reference computes V with W_K.
    float* out = (float*)d_out;

    static int attn_smem_set = 0;
    if (!attn_smem_set) {
        cudaFuncSetAttribute(attn_mma,
                             cudaFuncAttributeMaxDynamicSharedMemorySize, 69632);
        attn_smem_set = 1;
    }

    prep_w  <<<32, 256>>>(Wq, Wk);
    proj_mma<<<256, 256>>>(x);
    attn_mma<<<dim3(72, BSZ), 256, 69632>>>(out);
}